// round 10
// baseline (speedup 1.0000x reference)
#include <cuda_runtime.h>
#include <cuda_bf16.h>

// Cutout: out = x with a 16x16 box (centered at (cy[b], cx[b])) zeroed per image.
// x: [B=256, C=3, H=224, W=224] fp32 contiguous. cy, cx: [1,256] int32.
//
// Single-wave PERSISTENT grid: 592 CTAs (148 SMs x 4 resident @ 32 regs,
// 512 thr = 64 warps/SM = 100% occ), grid-stride loop (~8 iters). Each
// iteration is the proven R9 body: unroll x4 with 64-image stride (all
// sub-elements share (c,h,w)), front-batched MLP=4 warp-coalesced
// 128-bit streaming loads. Removes wave-transition dead time.

#define B 256
#define C 3
#define H 224
#define W 224
#define HALF 8

#define W4     (W / 4)            // 56
#define HW4    (H * W4)           // 12544
#define CHW4   (C * HW4)          // 37632
#define TOTAL4 (B * CHW4)         // 9,633,792
#define UNROLL 4
#define CHUNK  (TOTAL4 / UNROLL)  // 2,408,448 == 64 * CHW4 (b advances by 64)
#define NTHR   512
#define NBLK   (148 * 4)          // 592 CTAs -> one wave at full occupancy
#define STRIDE (NBLK * NTHR)      // 303,104 threads

__global__ void __launch_bounds__(NTHR) cutout_kernel(
    const float4* __restrict__ x,
    const int*    __restrict__ cy,
    const int*    __restrict__ cx,
    float4*       __restrict__ out)
{
    for (int i = blockIdx.x * NTHR + threadIdx.x; i < CHUNK; i += STRIDE) {
        // Decompose: i -> (b0, h, w). Sub-element j: b_j = b0 + 64*j, same (c,h,w).
        int b0   = i / CHW4;              // 0..63
        int rem  = i - b0 * CHW4;
        int hw4  = rem % HW4;
        int h    = hw4 / W4;
        int w    = (hw4 - h * W4) * 4;    // first of 4 consecutive W-coords

        // Front-batch 4 independent warp-coalesced 128-bit streaming loads (MLP=4).
        float4 v0 = __ldcs(x + i + 0 * CHUNK);
        float4 v1 = __ldcs(x + i + 1 * CHUNK);
        float4 v2 = __ldcs(x + i + 2 * CHUNK);
        float4 v3 = __ldcs(x + i + 3 * CHUNK);

        #define APPLY(v, j)                                                 \
            {                                                               \
                int yc = __ldg(&cy[b0 + 64 * (j)]);                         \
                if (h >= yc - HALF && h < yc + HALF) {                      \
                    int xc = __ldg(&cx[b0 + 64 * (j)]);                     \
                    int x0 = xc - HALF, x1 = xc + HALF;                     \
                    if (w + 0 >= x0 && w + 0 < x1) (v).x = 0.0f;            \
                    if (w + 1 >= x0 && w + 1 < x1) (v).y = 0.0f;            \
                    if (w + 2 >= x0 && w + 2 < x1) (v).z = 0.0f;            \
                    if (w + 3 >= x0 && w + 3 < x1) (v).w = 0.0f;            \
                }                                                           \
            }

        APPLY(v0, 0);
        APPLY(v1, 1);
        APPLY(v2, 2);
        APPLY(v3, 3);
        #undef APPLY

        __stcs(out + i + 0 * CHUNK, v0);
        __stcs(out + i + 1 * CHUNK, v1);
        __stcs(out + i + 2 * CHUNK, v2);
        __stcs(out + i + 3 * CHUNK, v3);
    }
}

extern "C" void kernel_launch(void* const* d_in, const int* in_sizes, int n_in,
                              void* d_out, int out_size)
{
    const float4* x   = (const float4*)d_in[0];
    const int*    cy  = (const int*)   d_in[1];
    const int*    cx  = (const int*)   d_in[2];
    float4*       out = (float4*)d_out;

    cutout_kernel<<<NBLK, NTHR>>>(x, cy, cx, out);
}

// round 11
// speedup vs baseline: 1.2154x; 1.2154x over previous
#include <cuda_runtime.h>
#include <cuda_bf16.h>

// Cutout: out = x with a 16x16 box (centered at (cy[b], cx[b])) zeroed per image.
// x: [B=256, C=3, H=224, W=224] fp32 contiguous. cy, cx: [1,256] int32.
//
// FINAL (R9 config — measured optimum of the sweep):
//   - warp-coalesced float4 streaming copy, unroll x4, stride = 64 images so
//     all 4 sub-elements share (c,h,w) -> one div/mod chain per thread
//   - front-batched independent loads (MLP=4) @ 32 regs -> ~80% occupancy
//     (sweep showed warps x MLP ~ const; this point maximizes DRAM%)
//   - exact grid (4704 x 512), no bounds check
//   - __ldcs/__stcs evict-first streaming hints (zero reuse)
//   - NOT persistent: independent CTAs pipeline across iterations better than
//     a grid-stride loop, whose loop-carried ordering drains MLP (R10: -15%).
// Measured: 41.6us ncu, 77.3% DRAM, 6.1TB/s = mixed R/W turnaround ceiling.

#define B 256
#define C 3
#define H 224
#define W 224
#define HALF 8

#define W4     (W / 4)            // 56
#define HW4    (H * W4)           // 12544
#define CHW4   (C * HW4)          // 37632
#define TOTAL4 (B * CHW4)         // 9,633,792
#define UNROLL 4
#define CHUNK  (TOTAL4 / UNROLL)  // 2,408,448 == 64 * CHW4 (b advances by 64)
#define NTHR   512
#define NBLK   (CHUNK / NTHR)     // 4704 (exact: 4704*512 = 2,408,448)

__global__ void __launch_bounds__(NTHR) cutout_kernel(
    const float4* __restrict__ x,
    const int*    __restrict__ cy,
    const int*    __restrict__ cx,
    float4*       __restrict__ out)
{
    int i = blockIdx.x * NTHR + threadIdx.x;   // exact grid, no bounds check

    // Decompose once: i -> (b0, h, w). Sub-element j: b_j = b0 + 64*j, same (c,h,w).
    int b0   = i / CHW4;              // 0..63
    int rem  = i - b0 * CHW4;
    int hw4  = rem % HW4;
    int h    = hw4 / W4;
    int w    = (hw4 - h * W4) * 4;    // first of 4 consecutive W-coords

    // Front-batch 4 independent warp-coalesced 128-bit streaming loads (MLP=4).
    float4 v0 = __ldcs(x + i + 0 * CHUNK);
    float4 v1 = __ldcs(x + i + 1 * CHUNK);
    float4 v2 = __ldcs(x + i + 2 * CHUNK);
    float4 v3 = __ldcs(x + i + 3 * CHUNK);

    #define APPLY(v, j)                                                     \
        {                                                                   \
            int yc = __ldg(&cy[b0 + 64 * (j)]);                             \
            if (h >= yc - HALF && h < yc + HALF) {                          \
                int xc = __ldg(&cx[b0 + 64 * (j)]);                         \
                int x0 = xc - HALF, x1 = xc + HALF;                         \
                if (w + 0 >= x0 && w + 0 < x1) (v).x = 0.0f;                \
                if (w + 1 >= x0 && w + 1 < x1) (v).y = 0.0f;                \
                if (w + 2 >= x0 && w + 2 < x1) (v).z = 0.0f;                \
                if (w + 3 >= x0 && w + 3 < x1) (v).w = 0.0f;                \
            }                                                               \
        }

    APPLY(v0, 0);
    APPLY(v1, 1);
    APPLY(v2, 2);
    APPLY(v3, 3);
    #undef APPLY

    __stcs(out + i + 0 * CHUNK, v0);
    __stcs(out + i + 1 * CHUNK, v1);
    __stcs(out + i + 2 * CHUNK, v2);
    __stcs(out + i + 3 * CHUNK, v3);
}

extern "C" void kernel_launch(void* const* d_in, const int* in_sizes, int n_in,
                              void* d_out, int out_size)
{
    const float4* x   = (const float4*)d_in[0];
    const int*    cy  = (const int*)   d_in[1];
    const int*    cx  = (const int*)   d_in[2];
    float4*       out = (float4*)d_out;

    cutout_kernel<<<NBLK, NTHR>>>(x, cy, cx, out);
}